// round 1
// baseline (speedup 1.0000x reference)
#include <cuda_runtime.h>
#include <math.h>

// Problem constants
#define BB 2
#define CC 128
#define HH 64
#define WW 64
#define NH 4
#define DH 32
#define KS 7
#define TOKENS (BB*HH*WW)   // 8192
#define HK (HH-KS)          // 57

// Scratch (device globals: no allocation allowed)
__device__ float g_y[TOKENS*CC];       // NHWC activations
__device__ float g_qkv[TOKENS*3*CC];   // qkv per layer
__device__ float g_att[TOKENS*CC];     // attention output

// ---------------------------------------------------------------------------
// NCHW -> NHWC transpose (per batch: [128, 4096] -> [4096, 128])
// ---------------------------------------------------------------------------
__global__ void transpose_in_kernel(const float* __restrict__ x, float* __restrict__ y)
{
    __shared__ float tile[32][33];
    int b   = blockIdx.z;
    int hw0 = blockIdx.x * 32;
    int c0  = blockIdx.y * 32;
    int tx = threadIdx.x, ty = threadIdx.y;
    #pragma unroll
    for (int k = 0; k < 32; k += 8)
        tile[ty + k][tx] = x[((b*CC + c0 + ty + k) * (HH*WW)) + hw0 + tx];
    __syncthreads();
    #pragma unroll
    for (int k = 0; k < 32; k += 8)
        y[(b*(HH*WW) + hw0 + ty + k)*CC + c0 + tx] = tile[tx][ty + k];
}

// ---------------------------------------------------------------------------
// SGEMM: C[M,N] = A[M,128] @ W[N,128]^T + bias  (optionally scale q columns)
// BM=BN=64, KT=32, 256 threads, 4x4 per thread.
// ---------------------------------------------------------------------------
__global__ __launch_bounds__(256) void gemm_kernel(
    const float* __restrict__ A,
    const float* __restrict__ W,
    const float* __restrict__ bias,
    float* __restrict__ C,
    int N, int scale_q)
{
    __shared__ float As[64][33];
    __shared__ float Bs[64][33];
    int m0 = blockIdx.x * 64;
    int n0 = blockIdx.y * 64;
    int tid = threadIdx.x;
    int tx = tid & 15, ty = tid >> 4;

    float acc[4][4] = {};
    for (int k0 = 0; k0 < 128; k0 += 32) {
        #pragma unroll
        for (int i = 0; i < 8; i++) {
            int idx = tid + i*256;
            int r = idx >> 5, c = idx & 31;
            As[r][c] = A[(m0 + r)*128 + k0 + c];
            Bs[r][c] = W[(n0 + r)*128 + k0 + c];
        }
        __syncthreads();
        #pragma unroll
        for (int kk = 0; kk < 32; kk++) {
            float a[4], bv[4];
            #pragma unroll
            for (int u = 0; u < 4; u++) a[u]  = As[ty*4 + u][kk];
            #pragma unroll
            for (int v = 0; v < 4; v++) bv[v] = Bs[tx*4 + v][kk];
            #pragma unroll
            for (int u = 0; u < 4; u++)
                #pragma unroll
                for (int v = 0; v < 4; v++)
                    acc[u][v] = fmaf(a[u], bv[v], acc[u][v]);
        }
        __syncthreads();
    }

    const float qs = 0.17677669529663687f; // 1/sqrt(32)
    #pragma unroll
    for (int u = 0; u < 4; u++) {
        int row = m0 + ty*4 + u;
        #pragma unroll
        for (int v = 0; v < 4; v++) {
            int col = n0 + tx*4 + v;
            float val = acc[u][v] + bias[col];
            if (scale_q && col < 128) val *= qs;
            C[row*N + col] = val;
        }
    }
}

// ---------------------------------------------------------------------------
// Neighborhood attention: one block per pixel, one warp per head (d=32=warp).
// qkv: [TOKENS, 384] with q|k|v each [4 heads x 32], q pre-scaled.
// rpb: [4, 13, 13] for this layer.
// ---------------------------------------------------------------------------
__global__ __launch_bounds__(128) void attn_kernel(
    const float* __restrict__ qkv,
    const float* __restrict__ rpb,
    float* __restrict__ out)
{
    int tok = blockIdx.x;
    int b  = tok >> 12;
    int ij = tok & 4095;
    int i = ij >> 6, j = ij & 63;
    int h = threadIdx.x >> 5;
    int lane = threadIdx.x & 31;

    int si = i - (KS/2); si = si < 0 ? 0 : (si > HK ? HK : si);
    int sj = j - (KS/2); sj = sj < 0 ? 0 : (sj > HK ? HK : sj);
    int di = i - si, dj = j - sj;

    __shared__ float sq[NH][DH];
    __shared__ float sw[NH][64];

    sq[h][lane] = qkv[tok*384 + h*DH + lane];
    __syncwarp();

    // Each lane computes score for neighbor n=lane, and n=lane+32 (lanes<17).
    float sc0 = -1e30f, sc1 = -1e30f;
    {
        int n = lane;
        int p = n / KS, q = n % KS;
        const float* kp = qkv + (((b*HH + si + p)*WW) + sj + q)*384 + 128 + h*DH;
        float s = 0.f;
        #pragma unroll
        for (int d = 0; d < DH; d++) s = fmaf(sq[h][d], kp[d], s);
        s += rpb[(h*13 + (p + 6 - di))*13 + (q + 6 - dj)];
        sc0 = s;
    }
    if (lane < 17) {
        int n = lane + 32;
        int p = n / KS, q = n % KS;
        const float* kp = qkv + (((b*HH + si + p)*WW) + sj + q)*384 + 128 + h*DH;
        float s = 0.f;
        #pragma unroll
        for (int d = 0; d < DH; d++) s = fmaf(sq[h][d], kp[d], s);
        s += rpb[(h*13 + (p + 6 - di))*13 + (q + 6 - dj)];
        sc1 = s;
    }

    // softmax over 49 scores held across the warp
    float m = fmaxf(sc0, sc1);
    #pragma unroll
    for (int o = 16; o > 0; o >>= 1) m = fmaxf(m, __shfl_xor_sync(0xffffffffu, m, o));
    float e0 = __expf(sc0 - m);
    float e1 = (lane < 17) ? __expf(sc1 - m) : 0.f;
    float se = e0 + e1;
    #pragma unroll
    for (int o = 16; o > 0; o >>= 1) se += __shfl_xor_sync(0xffffffffu, se, o);
    float inv = 1.f / se;
    sw[h][lane]      = e0 * inv;
    sw[h][lane + 32] = e1 * inv;
    __syncwarp();

    // AV: lane = channel d, coalesced v loads
    float acc = 0.f;
    #pragma unroll
    for (int p = 0; p < KS; p++) {
        const float* vrow = qkv + (((b*HH + si + p)*WW) + sj)*384 + 256 + h*DH + lane;
        #pragma unroll
        for (int q = 0; q < KS; q++)
            acc = fmaf(sw[h][p*KS + q], vrow[q*384], acc);
    }
    out[tok*CC + h*DH + lane] = acc;
}

// ---------------------------------------------------------------------------
// LayerNorm over C + NHWC -> NCHW transpose-out.
// 32 tokens per block, 8 warps (4 tokens each), smem transpose for coalesced
// writes along W.
// ---------------------------------------------------------------------------
__global__ __launch_bounds__(256) void ln_out_kernel(
    const float* __restrict__ y,
    const float* __restrict__ gamma,
    const float* __restrict__ beta,
    float* __restrict__ out)
{
    __shared__ float sh[32][129];
    int tok0 = blockIdx.x * 32;
    int b   = tok0 >> 12;
    int hw0 = tok0 & 4095;
    int w = threadIdx.x >> 5, lane = threadIdx.x & 31;

    #pragma unroll
    for (int t = w*4; t < w*4 + 4; t++) {
        int tok = tok0 + t;
        float v0 = y[tok*CC + lane];
        float v1 = y[tok*CC + lane + 32];
        float v2 = y[tok*CC + lane + 64];
        float v3 = y[tok*CC + lane + 96];
        float s  = v0 + v1 + v2 + v3;
        float s2 = v0*v0 + v1*v1 + v2*v2 + v3*v3;
        #pragma unroll
        for (int o = 16; o > 0; o >>= 1) {
            s  += __shfl_xor_sync(0xffffffffu, s,  o);
            s2 += __shfl_xor_sync(0xffffffffu, s2, o);
        }
        float mu  = s * (1.f/128.f);
        float var = s2 * (1.f/128.f) - mu*mu;
        float rs  = rsqrtf(var + 1e-5f);
        sh[t][lane]      = (v0 - mu)*rs*gamma[lane]      + beta[lane];
        sh[t][lane + 32] = (v1 - mu)*rs*gamma[lane + 32] + beta[lane + 32];
        sh[t][lane + 64] = (v2 - mu)*rs*gamma[lane + 64] + beta[lane + 64];
        sh[t][lane + 96] = (v3 - mu)*rs*gamma[lane + 96] + beta[lane + 96];
    }
    __syncthreads();

    for (int c = w; c < CC; c += 8)
        out[((b*CC + c)*(HH*WW)) + hw0 + lane] = sh[lane][c];
}

// ---------------------------------------------------------------------------
// Launch
// ---------------------------------------------------------------------------
extern "C" void kernel_launch(void* const* d_in, const int* in_sizes, int n_in,
                              void* d_out, int out_size)
{
    const float* x      = (const float*)d_in[0];   // (2,128,64,64)
    const float* qkv_w  = (const float*)d_in[1];   // (2,384,128)
    const float* qkv_b  = (const float*)d_in[2];   // (2,384)
    const float* rpb    = (const float*)d_in[3];   // (2,4,13,13)
    const float* proj_w = (const float*)d_in[4];   // (2,128,128)
    const float* proj_b = (const float*)d_in[5];   // (2,128)
    const float* ln_g   = (const float*)d_in[6];   // (128)
    const float* ln_b   = (const float*)d_in[7];   // (128)
    float* out = (float*)d_out;

    float *y, *qkv, *att;
    cudaGetSymbolAddress((void**)&y,   g_y);
    cudaGetSymbolAddress((void**)&qkv, g_qkv);
    cudaGetSymbolAddress((void**)&att, g_att);

    // NCHW -> NHWC
    {
        dim3 grid(HH*WW/32, CC/32, BB), block(32, 8);
        transpose_in_kernel<<<grid, block>>>(x, y);
    }

    for (int l = 0; l < 2; l++) {
        // qkv = y @ qkv_w[l]^T + qkv_b[l]   (q columns scaled by 1/sqrt(32))
        {
            dim3 grid(TOKENS/64, 384/64);
            gemm_kernel<<<grid, 256>>>(y, qkv_w + l*384*128, qkv_b + l*384,
                                       qkv, 384, 1);
        }
        // neighborhood attention
        attn_kernel<<<TOKENS, 128>>>(qkv, rpb + l*NH*13*13, att);
        // y = att @ proj_w[l]^T + proj_b[l]
        {
            dim3 grid(TOKENS/64, 128/64);
            gemm_kernel<<<grid, 256>>>(att, proj_w + l*128*128, proj_b + l*128,
                                       y, 128, 0);
        }
    }

    // LayerNorm + NHWC -> NCHW
    ln_out_kernel<<<TOKENS/32, 256>>>(y, ln_g, ln_b, out);
}

// round 2
// speedup vs baseline: 2.7976x; 2.7976x over previous
#include <cuda_runtime.h>
#include <math.h>

// Problem constants
#define BB 2
#define CC 128
#define HH 64
#define WW 64
#define NH 4
#define DH 32
#define KS 7
#define TOKENS (BB*HH*WW)   // 8192

// Attention tile config
#define TI 8            // tile height (pixels)
#define TJ 4            // tile width
#define NROW 14         // smem neighborhood rows  (TI + KS - 1)
#define NCOL 10         // smem neighborhood cols  (TJ + KS - 1)
#define NPIX (NROW*NCOL) // 140

// Scratch (device globals: no allocation allowed)
__device__ float g_y[TOKENS*CC];       // NHWC activations
__device__ float g_qkv[TOKENS*3*CC];   // qkv per layer
__device__ float g_att[TOKENS*CC];     // attention output

// ---------------------------------------------------------------------------
// NCHW -> NHWC transpose (per batch: [128, 4096] -> [4096, 128])
// ---------------------------------------------------------------------------
__global__ void transpose_in_kernel(const float* __restrict__ x, float* __restrict__ y)
{
    __shared__ float tile[32][33];
    int b   = blockIdx.z;
    int hw0 = blockIdx.x * 32;
    int c0  = blockIdx.y * 32;
    int tx = threadIdx.x, ty = threadIdx.y;
    #pragma unroll
    for (int k = 0; k < 32; k += 8)
        tile[ty + k][tx] = x[((b*CC + c0 + ty + k) * (HH*WW)) + hw0 + tx];
    __syncthreads();
    #pragma unroll
    for (int k = 0; k < 32; k += 8)
        y[(b*(HH*WW) + hw0 + ty + k)*CC + c0 + tx] = tile[tx][ty + k];
}

// ---------------------------------------------------------------------------
// SGEMM: C[M,N] = A[M,128] @ W[N,128]^T + bias  (optionally scale q columns)
// BM=BN=64, KT=32, 256 threads, 4x4 per thread.
// ---------------------------------------------------------------------------
__global__ __launch_bounds__(256) void gemm_kernel(
    const float* __restrict__ A,
    const float* __restrict__ W,
    const float* __restrict__ bias,
    float* __restrict__ C,
    int N, int scale_q)
{
    __shared__ float As[64][33];
    __shared__ float Bs[64][33];
    int m0 = blockIdx.x * 64;
    int n0 = blockIdx.y * 64;
    int tid = threadIdx.x;
    int tx = tid & 15, ty = tid >> 4;

    float acc[4][4] = {};
    for (int k0 = 0; k0 < 128; k0 += 32) {
        #pragma unroll
        for (int i = 0; i < 8; i++) {
            int idx = tid + i*256;
            int r = idx >> 5, c = idx & 31;
            As[r][c] = A[(m0 + r)*128 + k0 + c];
            Bs[r][c] = W[(n0 + r)*128 + k0 + c];
        }
        __syncthreads();
        #pragma unroll
        for (int kk = 0; kk < 32; kk++) {
            float a[4], bv[4];
            #pragma unroll
            for (int u = 0; u < 4; u++) a[u]  = As[ty*4 + u][kk];
            #pragma unroll
            for (int v = 0; v < 4; v++) bv[v] = Bs[tx*4 + v][kk];
            #pragma unroll
            for (int u = 0; u < 4; u++)
                #pragma unroll
                for (int v = 0; v < 4; v++)
                    acc[u][v] = fmaf(a[u], bv[v], acc[u][v]);
        }
        __syncthreads();
    }

    const float qs = 0.17677669529663687f; // 1/sqrt(32)
    #pragma unroll
    for (int u = 0; u < 4; u++) {
        int row = m0 + ty*4 + u;
        #pragma unroll
        for (int v = 0; v < 4; v++) {
            int col = n0 + tx*4 + v;
            float val = acc[u][v] + bias[col];
            if (scale_q && col < 128) val *= qs;
            C[row*N + col] = val;
        }
    }
}

// ---------------------------------------------------------------------------
// Neighborhood attention v2 (smem-tiled).
// One block = one head x (8x4) pixel tile. 256 threads = 8 warps.
// K/V neighborhood (14x10 pixels) staged in shared memory with coalesced
// 128B row loads. Warp w handles tile row w (4 pixels).
// ---------------------------------------------------------------------------
__global__ __launch_bounds__(256) void attn_kernel(
    const float* __restrict__ qkv,
    const float* __restrict__ rpb,
    float* __restrict__ out)
{
    __shared__ float k_s[NPIX*33];   // +1 pad: QK reads different rows at same d
    __shared__ float v_s[NPIX*32];   // unpadded: AV reads lane=channel, conflict-free
    __shared__ float rpb_s[169];

    int j0 = blockIdx.x * TJ;
    int i0 = blockIdx.y * TI;
    int bh = blockIdx.z;          // b*NH + h
    int b  = bh >> 2;
    int h  = bh & 3;

    int tid  = threadIdx.x;
    int wid  = tid >> 5;
    int lane = tid & 31;

    int rbase = i0 - 3; rbase = rbase < 0 ? 0 : (rbase > HH-NROW ? HH-NROW : rbase);
    int cbase = j0 - 3; cbase = cbase < 0 ? 0 : (cbase > WW-NCOL ? WW-NCOL : cbase);

    // ---- stage K, V, rpb into smem (coalesced) ----
    for (int r = wid; r < NPIX; r += 8) {
        int gi = r / NCOL, gj = r % NCOL;
        const float* base = qkv + (((b*HH + rbase + gi)*WW) + cbase + gj)*384 + h*DH;
        k_s[r*33 + lane] = base[128 + lane];
        v_s[r*32 + lane] = base[256 + lane];
    }
    if (tid < 169) rpb_s[tid] = rpb[h*169 + tid];
    __syncthreads();

    int i  = i0 + wid;
    int si = i - 3; si = si < 0 ? 0 : (si > HH-KS ? HH-KS : si);
    int rb = si - rbase;
    int di = i - si;

    #pragma unroll
    for (int lj = 0; lj < TJ; lj++) {
        int j  = j0 + lj;
        int sj = j - 3; sj = sj < 0 ? 0 : (sj > WW-KS ? WW-KS : sj);
        int cb = sj - cbase;
        int dj = j - sj;
        int tok = (b*HH + i)*WW + j;

        // q in registers, broadcast via shuffle
        float q_vec = qkv[tok*384 + h*DH + lane];

        // ---- QK: lane computes neighbors n0=lane and n1=lane+32 ----
        int n0 = lane;
        int n1 = lane + 32; if (n1 > 48) n1 = 48;
        int p0 = n0 / KS, c0 = n0 % KS;
        int p1 = n1 / KS, c1 = n1 % KS;
        const float* k0 = k_s + ((rb + p0)*NCOL + cb + c0)*33;
        const float* k1 = k_s + ((rb + p1)*NCOL + cb + c1)*33;
        float s0 = 0.f, s1 = 0.f;
        #pragma unroll
        for (int d = 0; d < DH; d++) {
            float qd = __shfl_sync(0xffffffffu, q_vec, d);
            s0 = fmaf(qd, k0[d], s0);
            s1 = fmaf(qd, k1[d], s1);
        }
        s0 += rpb_s[(p0 + 6 - di)*13 + (c0 + 6 - dj)];
        s1 += rpb_s[(p1 + 6 - di)*13 + (c1 + 6 - dj)];

        // ---- softmax over 49 scores ----
        float m = fmaxf(s0, s1);
        #pragma unroll
        for (int o = 16; o > 0; o >>= 1) m = fmaxf(m, __shfl_xor_sync(0xffffffffu, m, o));
        float e0 = __expf(s0 - m);
        float e1 = (lane < 17) ? __expf(s1 - m) : 0.f;
        float se = e0 + e1;
        #pragma unroll
        for (int o = 16; o > 0; o >>= 1) se += __shfl_xor_sync(0xffffffffu, se, o);
        float inv = 1.f / se;
        float w0 = e0 * inv;
        float w1 = e1 * inv;

        // ---- AV: lane = channel d, weights broadcast via shuffle ----
        float acc = 0.f;
        #pragma unroll
        for (int p = 0; p < KS; p++) {
            const float* vp = v_s + ((rb + p)*NCOL + cb)*32 + lane;
            #pragma unroll
            for (int q = 0; q < KS; q++) {
                int n = p*KS + q;
                float w = (n < 32) ? __shfl_sync(0xffffffffu, w0, n)
                                   : __shfl_sync(0xffffffffu, w1, n - 32);
                acc = fmaf(w, vp[q*32], acc);
            }
        }
        out[tok*CC + h*DH + lane] = acc;
    }
}

// ---------------------------------------------------------------------------
// LayerNorm over C + NHWC -> NCHW transpose-out.
// ---------------------------------------------------------------------------
__global__ __launch_bounds__(256) void ln_out_kernel(
    const float* __restrict__ y,
    const float* __restrict__ gamma,
    const float* __restrict__ beta,
    float* __restrict__ out)
{
    __shared__ float sh[32][129];
    int tok0 = blockIdx.x * 32;
    int b   = tok0 >> 12;
    int hw0 = tok0 & 4095;
    int w = threadIdx.x >> 5, lane = threadIdx.x & 31;

    #pragma unroll
    for (int t = w*4; t < w*4 + 4; t++) {
        int tok = tok0 + t;
        float v0 = y[tok*CC + lane];
        float v1 = y[tok*CC + lane + 32];
        float v2 = y[tok*CC + lane + 64];
        float v3 = y[tok*CC + lane + 96];
        float s  = v0 + v1 + v2 + v3;
        float s2 = v0*v0 + v1*v1 + v2*v2 + v3*v3;
        #pragma unroll
        for (int o = 16; o > 0; o >>= 1) {
            s  += __shfl_xor_sync(0xffffffffu, s,  o);
            s2 += __shfl_xor_sync(0xffffffffu, s2, o);
        }
        float mu  = s * (1.f/128.f);
        float var = s2 * (1.f/128.f) - mu*mu;
        float rs  = rsqrtf(var + 1e-5f);
        sh[t][lane]      = (v0 - mu)*rs*gamma[lane]      + beta[lane];
        sh[t][lane + 32] = (v1 - mu)*rs*gamma[lane + 32] + beta[lane + 32];
        sh[t][lane + 64] = (v2 - mu)*rs*gamma[lane + 64] + beta[lane + 64];
        sh[t][lane + 96] = (v3 - mu)*rs*gamma[lane + 96] + beta[lane + 96];
    }
    __syncthreads();

    for (int c = w; c < CC; c += 8)
        out[((b*CC + c)*(HH*WW)) + hw0 + lane] = sh[lane][c];
}

// ---------------------------------------------------------------------------
// Launch
// ---------------------------------------------------------------------------
extern "C" void kernel_launch(void* const* d_in, const int* in_sizes, int n_in,
                              void* d_out, int out_size)
{
    const float* x      = (const float*)d_in[0];   // (2,128,64,64)
    const float* qkv_w  = (const float*)d_in[1];   // (2,384,128)
    const float* qkv_b  = (const float*)d_in[2];   // (2,384)
    const float* rpb    = (const float*)d_in[3];   // (2,4,13,13)
    const float* proj_w = (const float*)d_in[4];   // (2,128,128)
    const float* proj_b = (const float*)d_in[5];   // (2,128)
    const float* ln_g   = (const float*)d_in[6];   // (128)
    const float* ln_b   = (const float*)d_in[7];   // (128)
    float* out = (float*)d_out;

    float *y, *qkv, *att;
    cudaGetSymbolAddress((void**)&y,   g_y);
    cudaGetSymbolAddress((void**)&qkv, g_qkv);
    cudaGetSymbolAddress((void**)&att, g_att);

    // NCHW -> NHWC
    {
        dim3 grid(HH*WW/32, CC/32, BB), block(32, 8);
        transpose_in_kernel<<<grid, block>>>(x, y);
    }

    for (int l = 0; l < 2; l++) {
        // qkv = y @ qkv_w[l]^T + qkv_b[l]   (q columns scaled by 1/sqrt(32))
        {
            dim3 grid(TOKENS/64, 384/64);
            gemm_kernel<<<grid, 256>>>(y, qkv_w + l*384*128, qkv_b + l*384,
                                       qkv, 384, 1);
        }
        // neighborhood attention (smem-tiled)
        {
            dim3 grid(WW/TJ, HH/TI, BB*NH);
            attn_kernel<<<grid, 256>>>(qkv, rpb + l*NH*13*13, att);
        }
        // y = att @ proj_w[l]^T + proj_b[l]
        {
            dim3 grid(TOKENS/64, 128/64);
            gemm_kernel<<<grid, 256>>>(att, proj_w + l*128*128, proj_b + l*128,
                                       y, 128, 0);
        }
    }

    // LayerNorm + NHWC -> NCHW
    ln_out_kernel<<<TOKENS/32, 256>>>(y, ln_g, ln_b, out);
}